// round 3
// baseline (speedup 1.0000x reference)
#include <cuda_runtime.h>
#include <math.h>

#define NN 100000
#define EE 1600000
#define TT (EE + NN)
#define IND 512
#define F1  256    // 8 heads * 32 ch
#define C2  64

// ---------------- scratch (device globals; no allocation allowed) ----------------
__device__ __align__(16) float g_h1[NN * F1];     // layer-1 linear output  [N,256]
__device__ __align__(16) float g_out1[NN * F1];   // layer-1 aggregated -> ELU'd (in place)
__device__ float    g_as1[NN * 8];
__device__ float    g_ad1[NN * 8];
__device__ unsigned g_m1[NN * 8];
__device__ float    g_den1[NN * 8];
__device__ __align__(16) float g_e1[(size_t)TT * 8]; // per-edge e, then ex
__device__ __align__(16) float g_h2[NN * C2];
__device__ float    g_as2[NN];
__device__ float    g_ad2[NN];
__device__ unsigned g_m2[NN];
__device__ float    g_den2[NN];
__device__ float    g_e2[TT];
__device__ int      g_src[EE];
__device__ int      g_dst[EE];
__device__ int      g_is64;

// order-preserving float<->uint encoding for atomicMax on floats
__device__ __forceinline__ unsigned encf(float f) {
    unsigned u = __float_as_uint(f);
    return (u & 0x80000000u) ? ~u : (u | 0x80000000u);
}
__device__ __forceinline__ float decf(unsigned u) {
    return __uint_as_float((u & 0x80000000u) ? (u & 0x7FFFFFFFu) : ~u);
}

__device__ __forceinline__ void red_add_v4(float* p, float4 v) {
    asm volatile("red.global.add.v4.f32 [%0], {%1,%2,%3,%4};"
                 :: "l"(p), "f"(v.x), "f"(v.y), "f"(v.z), "f"(v.w) : "memory");
}

// ---------------- edge-index dtype detection + conversion ----------------
// If the buffer is int64 (values < 2^31, nonneg), every odd 32-bit word of the
// first 1024 elements is 0. If int32, odd words are random node ids (~0 chance
// of all being 0). One block; deterministic.
__global__ void k_detect(const unsigned* __restrict__ raw) {
    __shared__ int ok;
    if (threadIdx.x == 0) ok = 1;
    __syncthreads();
    for (int i = threadIdx.x; i < 1024; i += blockDim.x)
        if (raw[2 * i + 1] != 0u) atomicAnd(&ok, 0);
    __syncthreads();
    if (threadIdx.x == 0) g_is64 = ok;
}

__global__ void k_convert(const unsigned* __restrict__ raw) {
    int t = blockIdx.x * blockDim.x + threadIdx.x;
    if (t >= EE) return;
    if (g_is64) {
        g_src[t] = (int)raw[(size_t)2 * t];
        g_dst[t] = (int)raw[(size_t)2 * (EE + t)];
    } else {
        g_src[t] = (int)raw[t];
        g_dst[t] = (int)raw[EE + t];
    }
}

// ---------------- zero/init ----------------
__global__ void k_zero_l1() {
    int i = blockIdx.x * blockDim.x + threadIdx.x;
    if (i < NN * F1) g_out1[i] = 0.f;
    if (i < NN * 8) { g_m1[i] = 0u; g_den1[i] = 0.f; }
}
__global__ void k_zero_l2(float* __restrict__ out) {
    int i = blockIdx.x * blockDim.x + threadIdx.x;
    if (i < NN * C2) out[i] = 0.f;
    if (i < NN) { g_m2[i] = 0u; g_den2[i] = 0.f; }
}

// ---------------- SGEMM: C[m][n] = sum_k A[m][k] * B[n][k]  (both K-major) ----------------
// BM=128 BN=64 BK=32, 256 threads, 8x4 per thread.
template <int WHICH>
__global__ void sgemm_nt(const float* __restrict__ Aext, const float* __restrict__ B,
                         int M, int K, int Nn) {
    const float* __restrict__ A = (WHICH == 0) ? Aext : g_out1;
    float* __restrict__ C = (WHICH == 0) ? g_h1 : g_h2;

    __shared__ float As[32][132];
    __shared__ float Bs[32][68];

    int t = threadIdx.x;
    int tx = t & 15;        // n-dir (16)
    int ty = t >> 4;        // m-dir (16)
    int bm0 = blockIdx.x * 128;
    int bn0 = blockIdx.y * 64;

    float acc[8][4];
#pragma unroll
    for (int i = 0; i < 8; i++)
#pragma unroll
        for (int j = 0; j < 4; j++) acc[i][j] = 0.f;

    for (int kt = 0; kt < K; kt += 32) {
#pragma unroll
        for (int i = 0; i < 4; i++) {
            int f = t + i * 256;
            int r = f >> 3, c4 = f & 7;
            int gm = bm0 + r;
            float4 v = make_float4(0.f, 0.f, 0.f, 0.f);
            if (gm < M) v = *(const float4*)&A[(size_t)gm * K + kt + c4 * 4];
            As[c4 * 4 + 0][r] = v.x;
            As[c4 * 4 + 1][r] = v.y;
            As[c4 * 4 + 2][r] = v.z;
            As[c4 * 4 + 3][r] = v.w;
        }
#pragma unroll
        for (int i = 0; i < 2; i++) {
            int f = t + i * 256;
            int r = f >> 3, c4 = f & 7;
            float4 v = *(const float4*)&B[(size_t)(bn0 + r) * K + kt + c4 * 4];
            Bs[c4 * 4 + 0][r] = v.x;
            Bs[c4 * 4 + 1][r] = v.y;
            Bs[c4 * 4 + 2][r] = v.z;
            Bs[c4 * 4 + 3][r] = v.w;
        }
        __syncthreads();
#pragma unroll
        for (int kk = 0; kk < 32; kk++) {
            float4 a0 = *(const float4*)&As[kk][ty * 8];
            float4 a1 = *(const float4*)&As[kk][ty * 8 + 4];
            float4 b0 = *(const float4*)&Bs[kk][tx * 4];
            float am[8] = {a0.x, a0.y, a0.z, a0.w, a1.x, a1.y, a1.z, a1.w};
            float bm[4] = {b0.x, b0.y, b0.z, b0.w};
#pragma unroll
            for (int i = 0; i < 8; i++)
#pragma unroll
                for (int j = 0; j < 4; j++) acc[i][j] += am[i] * bm[j];
        }
        __syncthreads();
    }
#pragma unroll
    for (int i = 0; i < 8; i++) {
        int gm = bm0 + ty * 8 + i;
        if (gm < M) {
            float4 v = make_float4(acc[i][0], acc[i][1], acc[i][2], acc[i][3]);
            *(float4*)&C[(size_t)gm * Nn + bn0 + tx * 4] = v;
        }
    }
}

// ---------------- attention logits per node ----------------
template <int L>
__global__ void k_attn(const float* __restrict__ att_s, const float* __restrict__ att_d) {
    constexpr int H = (L == 0) ? 8 : 1;
    constexpr int C = (L == 0) ? 32 : 64;
    const float* __restrict__ hmat = (L == 0) ? g_h1 : g_h2;
    float* __restrict__ os = (L == 0) ? g_as1 : g_as2;
    float* __restrict__ od = (L == 0) ? g_ad1 : g_ad2;

    int i = blockIdx.x * blockDim.x + threadIdx.x;
    if (i >= NN * H) return;
    int n = i / H, hh = i % H;
    const float* row = hmat + (size_t)n * (H * C) + hh * C;
    float s = 0.f, dv = 0.f;
#pragma unroll
    for (int c = 0; c < C; c++) {
        float v = row[c];
        s += v * att_s[hh * C + c];
        dv += v * att_d[hh * C + c];
    }
    os[i] = s;
    od[i] = dv;
}

// ---------------- edge pass 1: e = leaky_relu(a_s[src]+a_d[dst]); segment max ----------------
template <int L>
__global__ void k_edge_pass1() {
    constexpr int H = (L == 0) ? 8 : 1;
    const float* __restrict__ as_ = (L == 0) ? g_as1 : g_as2;
    const float* __restrict__ ad_ = (L == 0) ? g_ad1 : g_ad2;
    float* __restrict__ e = (L == 0) ? g_e1 : g_e2;
    unsigned* __restrict__ m = (L == 0) ? g_m1 : g_m2;

    int t = blockIdx.x * blockDim.x + threadIdx.x;
    if (t >= TT) return;
    int s, d;
    if (t < EE) { s = g_src[t]; d = g_dst[t]; }
    else        { s = t - EE; d = s; }
#pragma unroll
    for (int h = 0; h < H; h++) {
        float v = as_[s * H + h] + ad_[d * H + h];
        v = (v >= 0.f) ? v : 0.2f * v;
        e[(size_t)t * H + h] = v;
        atomicMax(&m[d * H + h], encf(v));
    }
}

// ---------------- edge pass 2: ex = exp(e - m[dst]); segment sum ----------------
template <int L>
__global__ void k_edge_pass2() {
    constexpr int H = (L == 0) ? 8 : 1;
    float* __restrict__ e = (L == 0) ? g_e1 : g_e2;
    const unsigned* __restrict__ m = (L == 0) ? g_m1 : g_m2;
    float* __restrict__ den = (L == 0) ? g_den1 : g_den2;

    int t = blockIdx.x * blockDim.x + threadIdx.x;
    if (t >= TT) return;
    int d;
    if (t < EE) d = g_dst[t];
    else        d = t - EE;
#pragma unroll
    for (int h = 0; h < H; h++) {
        float v = e[(size_t)t * H + h];
        float mm = decf(m[d * H + h]);
        float ex = __expf(v - mm);
        e[(size_t)t * H + h] = ex;
        atomicAdd(&den[d * H + h], ex);
    }
}

// ---------------- layer-1 scatter: out1[dst] += alpha * h1[src]  (warp per edge) ----------------
__global__ void k_scatter1() {
    int gt = blockIdx.x * blockDim.x + threadIdx.x;
    int w = gt >> 5, lane = gt & 31;
    if (w >= TT) return;
    int s, d;
    if (w < EE) { s = g_src[w]; d = g_dst[w]; }
    else        { s = w - EE; d = s; }

    float a = 0.f;
    if (lane < 8) a = g_e1[(size_t)w * 8 + lane] / (g_den1[d * 8 + lane] + 1e-16f);

    const float4* __restrict__ hs = (const float4*)&g_h1[(size_t)s * F1];
    float* __restrict__ od = &g_out1[(size_t)d * F1];
#pragma unroll
    for (int rep = 0; rep < 2; rep++) {
        int j = lane + rep * 32;                 // float4 index within [8][32] = 64 float4
        float al = __shfl_sync(0xffffffffu, a, j >> 3);  // head = (j*4)/32
        float4 v = hs[j];
        v.x *= al; v.y *= al; v.z *= al; v.w *= al;
        red_add_v4(od + j * 4, v);
    }
}

// ---------------- layer-2 scatter: out[dst] += alpha * h2[src]  (16 lanes per edge) ----------------
__global__ void k_scatter2(float* __restrict__ out) {
    int gt = blockIdx.x * blockDim.x + threadIdx.x;
    int w = gt >> 4, l = gt & 15;
    if (w >= TT) return;
    int s, d;
    if (w < EE) { s = g_src[w]; d = g_dst[w]; }
    else        { s = w - EE; d = s; }
    float a = g_e2[w] / (g_den2[d] + 1e-16f);
    float4 v = ((const float4*)&g_h2[(size_t)s * C2])[l];
    v.x *= a; v.y *= a; v.z *= a; v.w *= a;
    red_add_v4(&out[(size_t)d * C2 + l * 4], v);
}

// ---------------- elementwise ----------------
__global__ void k_bias_elu1(const float* __restrict__ b) {
    int i = blockIdx.x * blockDim.x + threadIdx.x;
    if (i >= NN * F1) return;
    float v = g_out1[i] + b[i & (F1 - 1)];
    g_out1[i] = (v > 0.f) ? v : (__expf(v) - 1.f);
}
__global__ void k_bias2(float* __restrict__ out, const float* __restrict__ b) {
    int i = blockIdx.x * blockDim.x + threadIdx.x;
    if (i >= NN * C2) return;
    out[i] += b[i & (C2 - 1)];
}

// ---------------- launch ----------------
extern "C" void kernel_launch(void* const* d_in, const int* in_sizes, int n_in,
                              void* d_out, int out_size) {
    const float*    x   = (const float*)d_in[0];
    const unsigned* ei  = (const unsigned*)d_in[1];   // raw words; dtype detected on device
    const float*    W1  = (const float*)d_in[2];
    const float*    as1 = (const float*)d_in[3];
    const float*    ad1 = (const float*)d_in[4];
    const float*    b1  = (const float*)d_in[5];
    const float*    W2  = (const float*)d_in[6];
    const float*    as2 = (const float*)d_in[7];
    const float*    ad2 = (const float*)d_in[8];
    const float*    b2  = (const float*)d_in[9];
    float* out = (float*)d_out;

    const int TPB = 256;

    // ----- edge index normalize (int64 or int32 -> int32 src/dst) -----
    k_detect<<<1, 256>>>(ei);
    k_convert<<<(EE + TPB - 1) / TPB, TPB>>>(ei);

    // ----- layer 1 -----
    k_zero_l1<<<(NN * F1 + TPB - 1) / TPB, TPB>>>();
    {
        dim3 g((NN + 127) / 128, F1 / 64);
        sgemm_nt<0><<<g, 256>>>(x, W1, NN, IND, F1);
    }
    k_attn<0><<<(NN * 8 + TPB - 1) / TPB, TPB>>>(as1, ad1);
    k_edge_pass1<0><<<(TT + TPB - 1) / TPB, TPB>>>();
    k_edge_pass2<0><<<(TT + TPB - 1) / TPB, TPB>>>();
    k_scatter1<<<((size_t)TT * 32 + TPB - 1) / TPB, TPB>>>();
    k_bias_elu1<<<(NN * F1 + TPB - 1) / TPB, TPB>>>(b1);

    // ----- layer 2 -----
    {
        dim3 g((NN + 127) / 128, C2 / 64);
        sgemm_nt<1><<<g, 256>>>(nullptr, W2, NN, F1, C2);
    }
    k_attn<1><<<(NN + TPB - 1) / TPB, TPB>>>(as2, ad2);
    k_zero_l2<<<(NN * C2 + TPB - 1) / TPB, TPB>>>(out);
    k_edge_pass1<1><<<(TT + TPB - 1) / TPB, TPB>>>();
    k_edge_pass2<1><<<(TT + TPB - 1) / TPB, TPB>>>();
    k_scatter2<<<((size_t)TT * 16 + TPB - 1) / TPB, TPB>>>(out);
    k_bias2<<<(NN * C2 + TPB - 1) / TPB, TPB>>>(out, b2);
}

// round 5
// speedup vs baseline: 1.0557x; 1.0557x over previous
#include <cuda_runtime.h>
#include <math.h>

#define NN 100000
#define EE 1600000
#define TT (EE + NN)
#define IND 512
#define F1  256    // 8 heads * 32 ch
#define C2  64

// ---------------- scratch (device globals; no allocation allowed) ----------------
__device__ __align__(16) float g_h1[NN * F1];     // layer-1 linear output  [N,256]
__device__ __align__(16) float g_out1[NN * F1];   // layer-1 accumulator -> finalized in place
__device__ float    g_as1[NN * 8];
__device__ float    g_ad1[NN * 8];
__device__ unsigned g_m1[NN * 8];
__device__ float    g_den1[NN * 8];
__device__ __align__(16) float g_h2[NN * C2];
__device__ float    g_as2[NN];
__device__ float    g_ad2[NN];
__device__ unsigned g_m2[NN];
__device__ float    g_den2[NN];
__device__ int      g_src[EE];
__device__ int      g_dst[EE];
__device__ int      g_is64;

// order-preserving float<->uint encoding for atomicMax on floats
__device__ __forceinline__ unsigned encf(float f) {
    unsigned u = __float_as_uint(f);
    return (u & 0x80000000u) ? ~u : (u | 0x80000000u);
}
__device__ __forceinline__ float decf(unsigned u) {
    return __uint_as_float((u & 0x80000000u) ? (u & 0x7FFFFFFFu) : ~u);
}

__device__ __forceinline__ void red_add_v4(float* p, float4 v) {
    asm volatile("red.global.add.v4.f32 [%0], {%1,%2,%3,%4};"
                 :: "l"(p), "f"(v.x), "f"(v.y), "f"(v.z), "f"(v.w) : "memory");
}

// ---------------- edge-index dtype detection + conversion ----------------
__global__ void k_detect(const unsigned* __restrict__ raw) {
    __shared__ int ok;
    if (threadIdx.x == 0) ok = 1;
    __syncthreads();
    for (int i = threadIdx.x; i < 1024; i += blockDim.x)
        if (raw[2 * i + 1] != 0u) atomicAnd(&ok, 0);
    __syncthreads();
    if (threadIdx.x == 0) g_is64 = ok;
}

__global__ void k_convert(const unsigned* __restrict__ raw) {
    int t = blockIdx.x * blockDim.x + threadIdx.x;
    if (t >= EE) return;
    if (g_is64) {
        g_src[t] = (int)raw[(size_t)2 * t];
        g_dst[t] = (int)raw[(size_t)2 * (EE + t)];
    } else {
        g_src[t] = (int)raw[t];
        g_dst[t] = (int)raw[EE + t];
    }
}

// ---------------- zero/init ----------------
__global__ void k_zero_l1() {
    int i = blockIdx.x * blockDim.x + threadIdx.x;
    if (i < NN * F1) g_out1[i] = 0.f;
    if (i < NN * 8) { g_m1[i] = 0u; g_den1[i] = 0.f; }
}
__global__ void k_zero_l2(float* __restrict__ out) {
    int i = blockIdx.x * blockDim.x + threadIdx.x;
    if (i < NN * C2) out[i] = 0.f;
    if (i < NN) { g_m2[i] = 0u; g_den2[i] = 0.f; }
}

// ---------------- SGEMM1: 128x128 tile, 8x8/thread. C[m][n]=sum_k A[m][k]*B[n][k] ----------------
// M=NN, K=512, N=256 (both operands K-major). C = g_h1.
__global__ void sgemm128(const float* __restrict__ A, const float* __restrict__ B, int M) {
    const int K = IND, Nn = F1;
    __shared__ float As[16][132];
    __shared__ float Bs[16][132];

    int t = threadIdx.x;
    int tx = t & 15;        // n-dir
    int ty = t >> 4;        // m-dir
    int bm0 = blockIdx.x * 128;
    int bn0 = blockIdx.y * 128;

    float acc[8][8];
#pragma unroll
    for (int i = 0; i < 8; i++)
#pragma unroll
        for (int j = 0; j < 8; j++) acc[i][j] = 0.f;

    for (int kt = 0; kt < K; kt += 16) {
#pragma unroll
        for (int i = 0; i < 2; i++) {
            int f = t + i * 256;
            int r = f >> 2, c4 = f & 3;          // 4 float4 per 16-wide row
            int gm = bm0 + r;
            float4 v = make_float4(0.f, 0.f, 0.f, 0.f);
            if (gm < M) v = *(const float4*)&A[(size_t)gm * K + kt + c4 * 4];
            As[c4 * 4 + 0][r] = v.x;
            As[c4 * 4 + 1][r] = v.y;
            As[c4 * 4 + 2][r] = v.z;
            As[c4 * 4 + 3][r] = v.w;
        }
#pragma unroll
        for (int i = 0; i < 2; i++) {
            int f = t + i * 256;
            int r = f >> 2, c4 = f & 3;
            float4 v = *(const float4*)&B[(size_t)(bn0 + r) * K + kt + c4 * 4];
            Bs[c4 * 4 + 0][r] = v.x;
            Bs[c4 * 4 + 1][r] = v.y;
            Bs[c4 * 4 + 2][r] = v.z;
            Bs[c4 * 4 + 3][r] = v.w;
        }
        __syncthreads();
#pragma unroll
        for (int kk = 0; kk < 16; kk++) {
            float4 a0 = *(const float4*)&As[kk][ty * 8];
            float4 a1 = *(const float4*)&As[kk][ty * 8 + 4];
            float4 b0 = *(const float4*)&Bs[kk][tx * 8];
            float4 b1 = *(const float4*)&Bs[kk][tx * 8 + 4];
            float am[8] = {a0.x, a0.y, a0.z, a0.w, a1.x, a1.y, a1.z, a1.w};
            float bn_[8] = {b0.x, b0.y, b0.z, b0.w, b1.x, b1.y, b1.z, b1.w};
#pragma unroll
            for (int i = 0; i < 8; i++)
#pragma unroll
                for (int j = 0; j < 8; j++) acc[i][j] += am[i] * bn_[j];
        }
        __syncthreads();
    }
#pragma unroll
    for (int i = 0; i < 8; i++) {
        int gm = bm0 + ty * 8 + i;
        if (gm < M) {
            float* c = &g_h1[(size_t)gm * Nn + bn0 + tx * 8];
            *(float4*)c = make_float4(acc[i][0], acc[i][1], acc[i][2], acc[i][3]);
            *(float4*)(c + 4) = make_float4(acc[i][4], acc[i][5], acc[i][6], acc[i][7]);
        }
    }
}

// ---------------- SGEMM2 (128x64 tile, 8x4/thread): A=g_out1 -> g_h2 ----------------
__global__ void sgemm_nt2(const float* __restrict__ B, int M, int K, int Nn) {
    const float* __restrict__ A = g_out1;
    float* __restrict__ C = g_h2;

    __shared__ float As[32][132];
    __shared__ float Bs[32][68];

    int t = threadIdx.x;
    int tx = t & 15;
    int ty = t >> 4;
    int bm0 = blockIdx.x * 128;
    int bn0 = blockIdx.y * 64;

    float acc[8][4];
#pragma unroll
    for (int i = 0; i < 8; i++)
#pragma unroll
        for (int j = 0; j < 4; j++) acc[i][j] = 0.f;

    for (int kt = 0; kt < K; kt += 32) {
#pragma unroll
        for (int i = 0; i < 4; i++) {
            int f = t + i * 256;
            int r = f >> 3, c4 = f & 7;
            int gm = bm0 + r;
            float4 v = make_float4(0.f, 0.f, 0.f, 0.f);
            if (gm < M) v = *(const float4*)&A[(size_t)gm * K + kt + c4 * 4];
            As[c4 * 4 + 0][r] = v.x;
            As[c4 * 4 + 1][r] = v.y;
            As[c4 * 4 + 2][r] = v.z;
            As[c4 * 4 + 3][r] = v.w;
        }
#pragma unroll
        for (int i = 0; i < 2; i++) {
            int f = t + i * 256;
            int r = f >> 3, c4 = f & 7;
            float4 v = *(const float4*)&B[(size_t)(bn0 + r) * K + kt + c4 * 4];
            Bs[c4 * 4 + 0][r] = v.x;
            Bs[c4 * 4 + 1][r] = v.y;
            Bs[c4 * 4 + 2][r] = v.z;
            Bs[c4 * 4 + 3][r] = v.w;
        }
        __syncthreads();
#pragma unroll
        for (int kk = 0; kk < 32; kk++) {
            float4 a0 = *(const float4*)&As[kk][ty * 8];
            float4 a1 = *(const float4*)&As[kk][ty * 8 + 4];
            float4 b0 = *(const float4*)&Bs[kk][tx * 4];
            float am[8] = {a0.x, a0.y, a0.z, a0.w, a1.x, a1.y, a1.z, a1.w};
            float bm[4] = {b0.x, b0.y, b0.z, b0.w};
#pragma unroll
            for (int i = 0; i < 8; i++)
#pragma unroll
                for (int j = 0; j < 4; j++) acc[i][j] += am[i] * bm[j];
        }
        __syncthreads();
    }
#pragma unroll
    for (int i = 0; i < 8; i++) {
        int gm = bm0 + ty * 8 + i;
        if (gm < M) {
            float4 v = make_float4(acc[i][0], acc[i][1], acc[i][2], acc[i][3]);
            *(float4*)&C[(size_t)gm * Nn + bn0 + tx * 4] = v;
        }
    }
}

// ---------------- attention logits per node ----------------
template <int L>
__global__ void k_attn(const float* __restrict__ att_s, const float* __restrict__ att_d) {
    constexpr int H = (L == 0) ? 8 : 1;
    constexpr int C = (L == 0) ? 32 : 64;
    const float* __restrict__ hmat = (L == 0) ? g_h1 : g_h2;
    float* __restrict__ os = (L == 0) ? g_as1 : g_as2;
    float* __restrict__ od = (L == 0) ? g_ad1 : g_ad2;

    int i = blockIdx.x * blockDim.x + threadIdx.x;
    if (i >= NN * H) return;
    int n = i / H, hh = i % H;
    const float* row = hmat + (size_t)n * (H * C) + hh * C;
    float s = 0.f, dv = 0.f;
#pragma unroll
    for (int c = 0; c < C; c++) {
        float v = row[c];
        s += v * att_s[hh * C + c];
        dv += v * att_d[hh * C + c];
    }
    os[i] = s;
    od[i] = dv;
}

// ---------------- edge max pass: atomicMax(m[dst], leaky(as[src]+ad[dst])) ----------------
template <int L>
__global__ void k_edge_max() {
    constexpr int H = (L == 0) ? 8 : 1;
    const float* __restrict__ as_ = (L == 0) ? g_as1 : g_as2;
    const float* __restrict__ ad_ = (L == 0) ? g_ad1 : g_ad2;
    unsigned* __restrict__ m = (L == 0) ? g_m1 : g_m2;

    int t = blockIdx.x * blockDim.x + threadIdx.x;
    if (t >= TT) return;
    int s, d;
    if (t < EE) { s = g_src[t]; d = g_dst[t]; }
    else        { s = t - EE; d = s; }
#pragma unroll
    for (int h = 0; h < H; h++) {
        float v = as_[s * H + h] + ad_[d * H + h];
        v = (v >= 0.f) ? v : 0.2f * v;
        atomicMax(&m[d * H + h], encf(v));
    }
}

// ---------------- fused L1: ex=exp(e-m[dst]); den+=ex; out1[dst]+=ex*h1[src] (warp/edge) ----------------
__global__ void k_scatter1() {
    int gt = blockIdx.x * blockDim.x + threadIdx.x;
    int w = gt >> 5, lane = gt & 31;
    if (w >= TT) return;
    int s, d;
    if (w < EE) { s = g_src[w]; d = g_dst[w]; }
    else        { s = w - EE; d = s; }

    float a = 0.f;
    if (lane < 8) {
        float v = g_as1[s * 8 + lane] + g_ad1[d * 8 + lane];
        v = (v >= 0.f) ? v : 0.2f * v;
        a = __expf(v - decf(g_m1[d * 8 + lane]));
        atomicAdd(&g_den1[d * 8 + lane], a);
    }

    const float4* __restrict__ hs = (const float4*)&g_h1[(size_t)s * F1];
    float* __restrict__ od = &g_out1[(size_t)d * F1];
#pragma unroll
    for (int rep = 0; rep < 2; rep++) {
        int j = lane + rep * 32;                 // float4 index within [8][32] = 64 float4
        float al = __shfl_sync(0xffffffffu, a, j >> 3);  // head = (j*4)/32
        float4 v = hs[j];
        v.x *= al; v.y *= al; v.z *= al; v.w *= al;
        red_add_v4(od + j * 4, v);
    }
}

// ---------------- fused L2: ex; den2+=ex; out[dst]+=ex*h2[src] (16 lanes/edge) ----------------
__global__ void k_scatter2(float* __restrict__ out) {
    int gt = blockIdx.x * blockDim.x + threadIdx.x;
    int w = gt >> 4, l = gt & 15;
    if (w >= TT) return;
    int s, d;
    if (w < EE) { s = g_src[w]; d = g_dst[w]; }
    else        { s = w - EE; d = s; }

    float a = 0.f;
    if (l == 0) {
        float v = g_as2[s] + g_ad2[d];
        v = (v >= 0.f) ? v : 0.2f * v;
        a = __expf(v - decf(g_m2[d]));
        atomicAdd(&g_den2[d], a);
    }
    a = __shfl_sync(0xffffffffu, a, (threadIdx.x & 31) & ~15);  // broadcast from lane0 of half-warp

    float4 v = ((const float4*)&g_h2[(size_t)s * C2])[l];
    v.x *= a; v.y *= a; v.z *= a; v.w *= a;
    red_add_v4(&out[(size_t)d * C2 + l * 4], v);
}

// ---------------- finalize ----------------
__global__ void k_final1(const float* __restrict__ b) {
    int i = blockIdx.x * blockDim.x + threadIdx.x;
    if (i >= NN * F1) return;
    int n = i >> 8, h = (i >> 5) & 7;
    float v = g_out1[i] / (g_den1[n * 8 + h] + 1e-16f) + b[i & (F1 - 1)];
    g_out1[i] = (v > 0.f) ? v : (__expf(v) - 1.f);
}
__global__ void k_final2(float* __restrict__ out, const float* __restrict__ b) {
    int i = blockIdx.x * blockDim.x + threadIdx.x;
    if (i >= NN * C2) return;
    int n = i >> 6;
    out[i] = out[i] / (g_den2[n] + 1e-16f) + b[i & (C2 - 1)];
}

// ---------------- launch ----------------
extern "C" void kernel_launch(void* const* d_in, const int* in_sizes, int n_in,
                              void* d_out, int out_size) {
    const float*    x   = (const float*)d_in[0];
    const unsigned* ei  = (const unsigned*)d_in[1];   // raw words; dtype detected on device
    const float*    W1  = (const float*)d_in[2];
    const float*    as1 = (const float*)d_in[3];
    const float*    ad1 = (const float*)d_in[4];
    const float*    b1  = (const float*)d_in[5];
    const float*    W2  = (const float*)d_in[6];
    const float*    as2 = (const float*)d_in[7];
    const float*    ad2 = (const float*)d_in[8];
    const float*    b2  = (const float*)d_in[9];
    float* out = (float*)d_out;

    const int TPB = 256;

    // ----- edge index normalize (int64 or int32 -> int32 src/dst) -----
    k_detect<<<1, 256>>>(ei);
    k_convert<<<(EE + TPB - 1) / TPB, TPB>>>(ei);

    // ----- layer 1 -----
    k_zero_l1<<<(NN * F1 + TPB - 1) / TPB, TPB>>>();
    {
        dim3 g((NN + 127) / 128, F1 / 128);
        sgemm128<<<g, 256>>>(x, W1, NN);
    }
    k_attn<0><<<(NN * 8 + TPB - 1) / TPB, TPB>>>(as1, ad1);
    k_edge_max<0><<<(TT + TPB - 1) / TPB, TPB>>>();
    k_scatter1<<<((size_t)TT * 32 + TPB - 1) / TPB, TPB>>>();
    k_final1<<<(NN * F1 + TPB - 1) / TPB, TPB>>>(b1);

    // ----- layer 2 -----
    {
        dim3 g((NN + 127) / 128, C2 / 64);
        sgemm_nt2<<<g, 256>>>(W2, NN, F1, C2);
    }
    k_attn<1><<<(NN + TPB - 1) / TPB, TPB>>>(as2, ad2);
    k_zero_l2<<<(NN * C2 + TPB - 1) / TPB, TPB>>>(out);
    k_edge_max<1><<<(TT + TPB - 1) / TPB, TPB>>>();
    k_scatter2<<<((size_t)TT * 16 + TPB - 1) / TPB, TPB>>>(out);
    k_final2<<<(NN * C2 + TPB - 1) / TPB, TPB>>>(out, b2);
}